// round 10
// baseline (speedup 1.0000x reference)
#include <cuda_runtime.h>
#include <cstdint>

// MC_Module_Batch: bilinear backward warp + weight + sum over R.
// cp.async.bulk (TMA-engine) row-tile staging, 3-stage mbarrier ring.
// pred [B,R,C,H,W], mv [B,R,2,H,W] (quarter-pel), weight [B,R,1,H,W] -> out [B,C,H,W]

#define Bv 4
#define Rv 2
#define Cv 19
#define Hv 256
#define Wv 512
#define HW (Hv * Wv)

#define PADY 9
#define TROWS (32 + 2 * PADY + 1)     // 51
#define TCOLS 56                       // window pad x: 12 left / 12 right (clamped)
#define TSZ   (TROWS * TCOLS)          // 2856 floats
#define NSTAGE 3
#define ROW_BYTES (TCOLS * 4)          // 224 (16B multiple)
#define TX_BYTES  (2 * TROWS * ROW_BYTES)   // 22848 per stage
#define SMEM_FLOATS (NSTAGE * 2 * TSZ)
#define SMEM_BYTES  (SMEM_FLOATS * 4 + NSTAGE * 8)

__device__ __forceinline__ void bulk_row(uint32_t dst, const void* src,
                                         uint32_t mbar) {
    asm volatile(
        "cp.async.bulk.shared::cta.global.mbarrier::complete_tx::bytes "
        "[%0], [%1], %2, [%3];"
        :: "r"(dst), "l"(src), "n"(ROW_BYTES), "r"(mbar) : "memory");
}
__device__ __forceinline__ void mbar_init(uint32_t mbar, uint32_t cnt) {
    asm volatile("mbarrier.init.shared.b64 [%0], %1;" :: "r"(mbar), "r"(cnt) : "memory");
}
__device__ __forceinline__ void mbar_expect_tx(uint32_t mbar, uint32_t bytes) {
    asm volatile("mbarrier.arrive.expect_tx.shared.b64 _, [%0], %1;"
                 :: "r"(mbar), "r"(bytes) : "memory");
}
__device__ __forceinline__ void mbar_wait(uint32_t mbar, uint32_t parity) {
    asm volatile(
        "{\n\t.reg .pred P;\n\t"
        "WL_%=:\n\t"
        "mbarrier.try_wait.parity.acquire.cta.shared::cta.b64 P, [%0], %1, 0x989680;\n\t"
        "@P bra.uni WD_%=;\n\t"
        "bra.uni WL_%=;\n\t"
        "WD_%=:\n\t}"
        :: "r"(mbar), "r"(parity) : "memory");
}

__global__ __launch_bounds__(256, 3)
void mc_warp_kernel(const float* __restrict__ pred,
                    const float* __restrict__ mv,
                    const float* __restrict__ wgt,
                    float* __restrict__ out)
{
    extern __shared__ __align__(16) float smem[];   // [NSTAGE][2][TSZ] + mbarriers
    const uint32_t smem_u32 = (uint32_t)__cvta_generic_to_shared(smem);
    const uint32_t mbar0 = smem_u32 + SMEM_FLOATS * 4;

    const int tid = threadIdx.x;
    const int tx  = tid & 31;
    const int ty  = tid >> 5;            // 0..7
    const int bx  = blockIdx.x, by = blockIdx.y, b = blockIdx.z;
    const int x0blk = bx * 32;
    const int y0blk = by * 32;
    const int x = x0blk + tx;
    const int wbase = min(max(x0blk - 12, 0), Wv - TCOLS);  // mult of 4 -> 16B aligned
    const int rowbase = y0blk - PADY;

    // ---- Precompute taps (4 px/thread, 2 r) ----
    // Fast: tile index of top-left tap (UNCLAMPED coords); taps at +0,+1,+TCOLS,+TCOLS+1.
    //   Invalid-coordinate taps carry exactly-zero weight; tile rows are clamped dups
    //   (finite), so result is exact.
    // Fallback (bit30): low17 = clamped global idx, bit20=dx, bit21=dy.
    float w4[4][2][4];
    int   idesc[4][2];
    int   fall = 0;
#pragma unroll
    for (int k = 0; k < 4; ++k) {
        const int y = y0blk + ty + 8 * k;
        const int pix = y * Wv + x;
#pragma unroll
        for (int r = 0; r < Rv; ++r) {
            const int nr = b * Rv + r;
            const float mvx = __ldg(mv + (size_t)(nr * 2) * HW + pix) * 0.25f;
            const float mvy = __ldg(mv + (size_t)(nr * 2 + 1) * HW + pix) * 0.25f;
            const float w   = __ldg(wgt + (size_t)nr * HW + pix);

            const float gx = (float)x + mvx;
            const float gy = (float)y + mvy;
            const float x0f = floorf(gx), y0f = floorf(gy);
            const float wx1 = gx - x0f, wx0 = 1.0f - wx1;
            const float wy1 = gy - y0f, wy0 = 1.0f - wy1;

            const int x0 = (int)x0f, y0 = (int)y0f;
            const int x1 = x0 + 1,   y1 = y0 + 1;

            const float vx0 = ((unsigned)x0 < (unsigned)Wv) ? 1.0f : 0.0f;
            const float vx1 = ((unsigned)x1 < (unsigned)Wv) ? 1.0f : 0.0f;
            const float vy0 = ((unsigned)y0 < (unsigned)Hv) ? 1.0f : 0.0f;
            const float vy1 = ((unsigned)y1 < (unsigned)Hv) ? 1.0f : 0.0f;

            w4[k][r][0] = wy0 * wx0 * vy0 * vx0 * w;
            w4[k][r][1] = wy0 * wx1 * vy0 * vx1 * w;
            w4[k][r][2] = wy1 * wx0 * vy1 * vx0 * w;
            w4[k][r][3] = wy1 * wx1 * vy1 * vx1 * w;

            const int tT = y0 - rowbase;   // UNCLAMPED
            const int tX = x0 - wbase;     // UNCLAMPED
            if ((unsigned)tT <= (TROWS - 2) && (unsigned)tX <= (TCOLS - 2)) {
                idesc[k][r] = tT * TCOLS + tX;
            } else {
                const int cx0 = min(max(x0, 0), Wv - 1);
                const int cx1 = min(max(x1, 0), Wv - 1);
                const int cy0 = min(max(y0, 0), Hv - 1);
                const int cy1 = min(max(y1, 0), Hv - 1);
                idesc[k][r] = 0x40000000 | ((cy1 - cy0) << 21)
                            | ((cx1 - cx0) << 20) | (cy0 * Wv + cx0);
                fall = 1;
            }
        }
    }

    const float* pb0 = pred + (size_t)(b * Rv + 0) * Cv * HW;
    const float* pb1 = pred + (size_t)(b * Rv + 1) * Cv * HW;
    float* ob = out + (size_t)b * Cv * HW + (size_t)(y0blk + ty) * Wv + x;

    // mbarrier init must precede any expect_tx/bulk — do before the OR-barrier.
    if (tid == 0) {
#pragma unroll
        for (int s = 0; s < NSTAGE; ++s) mbar_init(mbar0 + s * 8, 1);
    }
    const int anyfall = __syncthreads_or(fall);   // also orders mbar_init

    // issue channel c's tiles (both r) into stage s
    auto issue = [&](int c, int s) {
        if (tid == 0) mbar_expect_tx(mbar0 + s * 8, TX_BYTES);
        if (tid < 2 * TROWS) {
            const int r   = (tid >= TROWS) ? 1 : 0;
            const int row = tid - r * TROWS;
            const int gcy = min(max(rowbase + row, 0), Hv - 1);
            const float* src = (r ? pb1 : pb0) + (size_t)c * HW + gcy * Wv + wbase;
            const uint32_t dst = smem_u32 + (uint32_t)(((s * 2 + r) * TSZ + row * TCOLS) * 4);
            bulk_row(dst, src, mbar0 + s * 8);
        }
    };

    issue(0, 0);
    issue(1, 1);

    if (!anyfall) {
        for (int c = 0; c < Cv; ++c) {
            const int st = c % NSTAGE;
            mbar_wait(mbar0 + st * 8, (c / NSTAGE) & 1);

            const float* tbase = smem + st * 2 * TSZ;
            float* oc = ob + (size_t)c * HW;
#pragma unroll
            for (int k = 0; k < 4; ++k) {
                float s = 0.0f;
#pragma unroll
                for (int r = 0; r < Rv; ++r) {
                    const float* tb = tbase + r * TSZ + idesc[k][r];
                    s = fmaf(w4[k][r][0], tb[0],
                        fmaf(w4[k][r][1], tb[1],
                        fmaf(w4[k][r][2], tb[TCOLS],
                        fmaf(w4[k][r][3], tb[TCOLS + 1], s))));
                }
                oc[(size_t)(8 * k) * Wv] = s;
            }
            __syncthreads();                  // all done reading stage st
            if (c + 2 < Cv) issue(c + 2, (c + 2) % NSTAGE);
        }
    } else {
        for (int c = 0; c < Cv; ++c) {
            const int st = c % NSTAGE;
            mbar_wait(mbar0 + st * 8, (c / NSTAGE) & 1);

            const float* tbase = smem + st * 2 * TSZ;
            float* oc = ob + (size_t)c * HW;
#pragma unroll
            for (int k = 0; k < 4; ++k) {
                float s = 0.0f;
#pragma unroll
                for (int r = 0; r < Rv; ++r) {
                    const int d = idesc[k][r];
                    float t0v, t1v, b0v, b1v;
                    if (d < 0x40000000) {
                        const float* tb = tbase + r * TSZ + d;
                        t0v = tb[0];      t1v = tb[1];
                        b0v = tb[TCOLS];  b1v = tb[TCOLS + 1];
                    } else {
                        const int gT = d & 0x1FFFF;
                        const int dv = (d >> 20) & 1;
                        const int gB = gT + ((d >> 21) & 1) * Wv;
                        const float* pc = (r ? pb1 : pb0) + (size_t)c * HW;
                        t0v = __ldg(pc + gT);  t1v = __ldg(pc + gT + dv);
                        b0v = __ldg(pc + gB);  b1v = __ldg(pc + gB + dv);
                    }
                    s = fmaf(w4[k][r][0], t0v,
                        fmaf(w4[k][r][1], t1v,
                        fmaf(w4[k][r][2], b0v,
                        fmaf(w4[k][r][3], b1v, s))));
                }
                oc[(size_t)(8 * k) * Wv] = s;
            }
            __syncthreads();
            if (c + 2 < Cv) issue(c + 2, (c + 2) % NSTAGE);
        }
    }
}

extern "C" void kernel_launch(void* const* d_in, const int* in_sizes, int n_in,
                              void* d_out, int out_size)
{
    const float* pred = (const float*)d_in[0];
    const float* mv   = (const float*)d_in[1];
    const float* wgt  = (const float*)d_in[2];
    float* out        = (float*)d_out;

    cudaFuncSetAttribute(mc_warp_kernel,
                         cudaFuncAttributeMaxDynamicSharedMemorySize, SMEM_BYTES);

    dim3 grid(Wv / 32, Hv / 32, Bv);   // 16 x 8 x 4 = 512 blocks
    mc_warp_kernel<<<grid, 256, SMEM_BYTES>>>(pred, mv, wgt, out);
}

// round 11
// speedup vs baseline: 1.3217x; 1.3217x over previous
#include <cuda_runtime.h>
#include <cstdint>

// MC_Module_Batch: bilinear backward warp + weight + sum over R.
// 2-stage cp.async pipeline, clamped tile window (single float4 loader),
// 4 CTAs/SM via dynamic smem + launch_bounds(256,4).
// pred [B,R,C,H,W], mv [B,R,2,H,W] (quarter-pel), weight [B,R,1,H,W] -> out [B,C,H,W]

#define Bv 4
#define Rv 2
#define Cv 19
#define Hv 256
#define Wv 512
#define HW (Hv * Wv)

#define PADY 8
#define TROWS (32 + 2 * PADY + 1)   // 49
#define TCOLS 64
#define TSZ   (TROWS * TCOLS)        // 3136 floats (12.25 KB)
#define TSZ4  (TSZ / 4)              // 784 float4
#define SMEM_BYTES (2 * 2 * TSZ * 4) // 50176 B

__device__ __forceinline__ void cp_async16(uint32_t smem, const void* g) {
    asm volatile("cp.async.cg.shared.global [%0], [%1], 16;" :: "r"(smem), "l"(g));
}
__device__ __forceinline__ void cp_commit() {
    asm volatile("cp.async.commit_group;");
}
template<int N> __device__ __forceinline__ void cp_wait() {
    asm volatile("cp.async.wait_group %0;" :: "n"(N));
}

__global__ __launch_bounds__(256, 4)
void mc_warp_kernel(const float* __restrict__ pred,
                    const float* __restrict__ mv,
                    const float* __restrict__ wgt,
                    float* __restrict__ out)
{
    extern __shared__ __align__(16) float smem[];   // [2 stages][2 r][TSZ]
    const uint32_t smem_u32 = (uint32_t)__cvta_generic_to_shared(smem);

    const int tid = threadIdx.x;
    const int tx  = tid & 31;
    const int ty  = tid >> 5;            // 0..7
    const int bx  = blockIdx.x, by = blockIdx.y, b = blockIdx.z;
    const int x0blk = bx * 32;
    const int y0blk = by * 32;
    const int x = x0blk + tx;
    // Clamped x-window: always in-bounds -> single float4 loader for ALL blocks.
    const int wbase = min(max(x0blk - 16, 0), Wv - TCOLS);
    const int rowbase = y0blk - PADY;    // rows clamped per-row at load

    // ---- Precompute taps (4 px/thread, 2 r) ----
    // Fast: tile index of top-left tap (UNCLAMPED coords); taps at
    //   +0, +1, +TCOLS, +TCOLS+1. Row-clamped tile data + exactly-zero weights
    //   on invalid taps keep this exact. Unsigned tX/tT checks route any tap
    //   outside the window (incl. x0 < wbase at border blocks) to fallback.
    // Fallback (bit30): low17 = clamped global idx, bit20=dx, bit21=dy.
    float w4[4][2][4];
    int   idesc[4][2];
    int   fall = 0;
#pragma unroll
    for (int k = 0; k < 4; ++k) {
        const int y = y0blk + ty + 8 * k;
        const int pix = y * Wv + x;
#pragma unroll
        for (int r = 0; r < Rv; ++r) {
            const int nr = b * Rv + r;
            const float mvx = __ldg(mv + (size_t)(nr * 2) * HW + pix) * 0.25f;
            const float mvy = __ldg(mv + (size_t)(nr * 2 + 1) * HW + pix) * 0.25f;
            const float w   = __ldg(wgt + (size_t)nr * HW + pix);

            const float gx = (float)x + mvx;
            const float gy = (float)y + mvy;
            const float x0f = floorf(gx), y0f = floorf(gy);
            const float wx1 = gx - x0f, wx0 = 1.0f - wx1;
            const float wy1 = gy - y0f, wy0 = 1.0f - wy1;

            const int x0 = (int)x0f, y0 = (int)y0f;
            const int x1 = x0 + 1,   y1 = y0 + 1;

            const float vx0 = ((unsigned)x0 < (unsigned)Wv) ? 1.0f : 0.0f;
            const float vx1 = ((unsigned)x1 < (unsigned)Wv) ? 1.0f : 0.0f;
            const float vy0 = ((unsigned)y0 < (unsigned)Hv) ? 1.0f : 0.0f;
            const float vy1 = ((unsigned)y1 < (unsigned)Hv) ? 1.0f : 0.0f;

            w4[k][r][0] = wy0 * wx0 * vy0 * vx0 * w;
            w4[k][r][1] = wy0 * wx1 * vy0 * vx1 * w;
            w4[k][r][2] = wy1 * wx0 * vy1 * vx0 * w;
            w4[k][r][3] = wy1 * wx1 * vy1 * vx1 * w;

            const int tT = y0 - rowbase;   // UNCLAMPED
            const int tX = x0 - wbase;     // UNCLAMPED
            if ((unsigned)tT <= (TROWS - 2) && (unsigned)tX <= (TCOLS - 2)) {
                idesc[k][r] = tT * TCOLS + tX;
            } else {
                const int cx0 = min(max(x0, 0), Wv - 1);
                const int cx1 = min(max(x1, 0), Wv - 1);
                const int cy0 = min(max(y0, 0), Hv - 1);
                const int cy1 = min(max(y1, 0), Hv - 1);
                idesc[k][r] = 0x40000000 | ((cy1 - cy0) << 21)
                            | ((cx1 - cx0) << 20) | (cy0 * Wv + cx0);
                fall = 1;
            }
        }
    }
    const int anyfall = __syncthreads_or(fall);

    const float* pb0 = pred + (size_t)(b * Rv + 0) * Cv * HW;
    const float* pb1 = pred + (size_t)(b * Rv + 1) * Cv * HW;
    const int wb4 = wbase >> 2;

    float* ob = out + (size_t)b * Cv * HW + (size_t)(y0blk + ty) * Wv + x;

    auto load_stage = [&](int c, int st) {
        const float4* s0 = (const float4*)(pb0 + (size_t)c * HW);
        const float4* s1 = (const float4*)(pb1 + (size_t)c * HW);
        const uint32_t d0 = smem_u32 + (uint32_t)(st * 2 * TSZ) * 4u;
#pragma unroll
        for (int i = tid; i < TSZ4; i += 256) {
            const int row = i >> 4;           // 16 float4 per tile row
            const int c4  = i & 15;
            const int gcy = min(max(rowbase + row, 0), Hv - 1);
            const int gi  = gcy * (Wv / 4) + wb4 + c4;
            cp_async16(d0 + (uint32_t)i * 16u, s0 + gi);
            cp_async16(d0 + (uint32_t)(TSZ * 4) + (uint32_t)i * 16u, s1 + gi);
        }
    };

    load_stage(0, 0);
    cp_commit();

    if (!anyfall) {
        for (int c = 0; c < Cv; ++c) {
            const int st = c & 1;
            if (c + 1 < Cv) { load_stage(c + 1, st ^ 1); cp_commit(); cp_wait<1>(); }
            else            { cp_wait<0>(); }
            __syncthreads();

            const float* tbase = smem + st * 2 * TSZ;
            float* oc = ob + (size_t)c * HW;
#pragma unroll
            for (int k = 0; k < 4; ++k) {
                float s = 0.0f;
#pragma unroll
                for (int r = 0; r < Rv; ++r) {
                    const float* tb = tbase + r * TSZ + idesc[k][r];
                    s = fmaf(w4[k][r][0], tb[0],
                        fmaf(w4[k][r][1], tb[1],
                        fmaf(w4[k][r][2], tb[TCOLS],
                        fmaf(w4[k][r][3], tb[TCOLS + 1], s))));
                }
                oc[(size_t)(8 * k) * Wv] = s;
            }
            __syncthreads();
        }
    } else {
        for (int c = 0; c < Cv; ++c) {
            const int st = c & 1;
            if (c + 1 < Cv) { load_stage(c + 1, st ^ 1); cp_commit(); cp_wait<1>(); }
            else            { cp_wait<0>(); }
            __syncthreads();

            const float* tbase = smem + st * 2 * TSZ;
            float* oc = ob + (size_t)c * HW;
#pragma unroll
            for (int k = 0; k < 4; ++k) {
                float s = 0.0f;
#pragma unroll
                for (int r = 0; r < Rv; ++r) {
                    const int d = idesc[k][r];
                    float t0v, t1v, b0v, b1v;
                    if (d < 0x40000000) {
                        const float* tb = tbase + r * TSZ + d;
                        t0v = tb[0];      t1v = tb[1];
                        b0v = tb[TCOLS];  b1v = tb[TCOLS + 1];
                    } else {
                        const int gT = d & 0x1FFFF;
                        const int dv = (d >> 20) & 1;
                        const int gB = gT + ((d >> 21) & 1) * Wv;
                        const float* pc = (r ? pb1 : pb0) + (size_t)c * HW;
                        t0v = __ldg(pc + gT);  t1v = __ldg(pc + gT + dv);
                        b0v = __ldg(pc + gB);  b1v = __ldg(pc + gB + dv);
                    }
                    s = fmaf(w4[k][r][0], t0v,
                        fmaf(w4[k][r][1], t1v,
                        fmaf(w4[k][r][2], b0v,
                        fmaf(w4[k][r][3], b1v, s))));
                }
                oc[(size_t)(8 * k) * Wv] = s;
            }
            __syncthreads();
        }
    }
}

extern "C" void kernel_launch(void* const* d_in, const int* in_sizes, int n_in,
                              void* d_out, int out_size)
{
    const float* pred = (const float*)d_in[0];
    const float* mv   = (const float*)d_in[1];
    const float* wgt  = (const float*)d_in[2];
    float* out        = (float*)d_out;

    cudaFuncSetAttribute(mc_warp_kernel,
                         cudaFuncAttributeMaxDynamicSharedMemorySize, SMEM_BYTES);

    dim3 grid(Wv / 32, Hv / 32, Bv);   // 16 x 8 x 4 = 512 blocks
    mc_warp_kernel<<<grid, 256, SMEM_BYTES>>>(pred, mv, wgt, out);
}

// round 12
// speedup vs baseline: 1.4237x; 1.0771x over previous
#include <cuda_runtime.h>
#include <cstdint>

// MC_Module_Batch: bilinear backward warp + weight + sum over R.
// 2-stage cp.async pipeline, clamped tile window, 32x16 output tile,
// 2 px/thread -> low regs -> 5 CTAs/SM.
// pred [B,R,C,H,W], mv [B,R,2,H,W] (quarter-pel), weight [B,R,1,H,W] -> out [B,C,H,W]

#define Bv 4
#define Rv 2
#define Cv 19
#define Hv 256
#define Wv 512
#define HW (Hv * Wv)

#define TILE_H 16
#define PADY 8
#define TROWS (TILE_H + 2 * PADY + 1)  // 33
#define TCOLS 64
#define TSZ   (TROWS * TCOLS)           // 2112 floats (8.25 KB)
#define TSZ4  (TSZ / 4)                 // 528 float4
#define SMEM_BYTES (2 * 2 * TSZ * 4)    // 33792 B

__device__ __forceinline__ void cp_async16(uint32_t smem, const void* g) {
    asm volatile("cp.async.cg.shared.global [%0], [%1], 16;" :: "r"(smem), "l"(g));
}
__device__ __forceinline__ void cp_commit() {
    asm volatile("cp.async.commit_group;");
}
template<int N> __device__ __forceinline__ void cp_wait() {
    asm volatile("cp.async.wait_group %0;" :: "n"(N));
}

__global__ __launch_bounds__(256, 5)
void mc_warp_kernel(const float* __restrict__ pred,
                    const float* __restrict__ mv,
                    const float* __restrict__ wgt,
                    float* __restrict__ out)
{
    extern __shared__ __align__(16) float smem[];   // [2 stages][2 r][TSZ]
    const uint32_t smem_u32 = (uint32_t)__cvta_generic_to_shared(smem);

    const int tid = threadIdx.x;
    const int tx  = tid & 31;
    const int ty  = tid >> 5;            // 0..7
    const int bx  = blockIdx.x, by = blockIdx.y, b = blockIdx.z;
    const int x0blk = bx * 32;
    const int y0blk = by * TILE_H;
    const int x = x0blk + tx;
    const int wbase = min(max(x0blk - 16, 0), Wv - TCOLS);  // clamped window
    const int rowbase = y0blk - PADY;

    // ---- Precompute taps (2 px/thread, 2 r) ----
    // Fast: tile index of top-left tap (UNCLAMPED coords); taps at
    //   +0, +1, +TCOLS, +TCOLS+1. Row-clamped tile + zero weights on invalid
    //   taps keep this exact; window-escaping taps -> exact global fallback.
    // Fallback (bit30): low17 = clamped global idx, bit20=dx, bit21=dy.
    float w4[2][2][4];
    int   idesc[2][2];
    int   fall = 0;
#pragma unroll
    for (int k = 0; k < 2; ++k) {
        const int y = y0blk + ty + 8 * k;
        const int pix = y * Wv + x;
#pragma unroll
        for (int r = 0; r < Rv; ++r) {
            const int nr = b * Rv + r;
            const float mvx = __ldg(mv + (size_t)(nr * 2) * HW + pix) * 0.25f;
            const float mvy = __ldg(mv + (size_t)(nr * 2 + 1) * HW + pix) * 0.25f;
            const float w   = __ldg(wgt + (size_t)nr * HW + pix);

            const float gx = (float)x + mvx;
            const float gy = (float)y + mvy;
            const float x0f = floorf(gx), y0f = floorf(gy);
            const float wx1 = gx - x0f, wx0 = 1.0f - wx1;
            const float wy1 = gy - y0f, wy0 = 1.0f - wy1;

            const int x0 = (int)x0f, y0 = (int)y0f;
            const int x1 = x0 + 1,   y1 = y0 + 1;

            const float vx0 = ((unsigned)x0 < (unsigned)Wv) ? 1.0f : 0.0f;
            const float vx1 = ((unsigned)x1 < (unsigned)Wv) ? 1.0f : 0.0f;
            const float vy0 = ((unsigned)y0 < (unsigned)Hv) ? 1.0f : 0.0f;
            const float vy1 = ((unsigned)y1 < (unsigned)Hv) ? 1.0f : 0.0f;

            w4[k][r][0] = wy0 * wx0 * vy0 * vx0 * w;
            w4[k][r][1] = wy0 * wx1 * vy0 * vx1 * w;
            w4[k][r][2] = wy1 * wx0 * vy1 * vx0 * w;
            w4[k][r][3] = wy1 * wx1 * vy1 * vx1 * w;

            const int tT = y0 - rowbase;   // UNCLAMPED
            const int tX = x0 - wbase;     // UNCLAMPED
            if ((unsigned)tT <= (TROWS - 2) && (unsigned)tX <= (TCOLS - 2)) {
                idesc[k][r] = tT * TCOLS + tX;
            } else {
                const int cx0 = min(max(x0, 0), Wv - 1);
                const int cx1 = min(max(x1, 0), Wv - 1);
                const int cy0 = min(max(y0, 0), Hv - 1);
                const int cy1 = min(max(y1, 0), Hv - 1);
                idesc[k][r] = 0x40000000 | ((cy1 - cy0) << 21)
                            | ((cx1 - cx0) << 20) | (cy0 * Wv + cx0);
                fall = 1;
            }
        }
    }
    const int anyfall = __syncthreads_or(fall);

    const float* pb0 = pred + (size_t)(b * Rv + 0) * Cv * HW;
    const float* pb1 = pred + (size_t)(b * Rv + 1) * Cv * HW;
    const int wb4 = wbase >> 2;

    float* ob = out + (size_t)b * Cv * HW + (size_t)(y0blk + ty) * Wv + x;

    auto load_stage = [&](int c, int st) {
        const float4* s0 = (const float4*)(pb0 + (size_t)c * HW);
        const float4* s1 = (const float4*)(pb1 + (size_t)c * HW);
        const uint32_t d0 = smem_u32 + (uint32_t)(st * 2 * TSZ) * 4u;
#pragma unroll
        for (int i = tid; i < TSZ4; i += 256) {
            const int row = i >> 4;           // 16 float4 per tile row
            const int c4  = i & 15;
            const int gcy = min(max(rowbase + row, 0), Hv - 1);
            const int gi  = gcy * (Wv / 4) + wb4 + c4;
            cp_async16(d0 + (uint32_t)i * 16u, s0 + gi);
            cp_async16(d0 + (uint32_t)(TSZ * 4) + (uint32_t)i * 16u, s1 + gi);
        }
    };

    load_stage(0, 0);
    cp_commit();

    if (!anyfall) {
        for (int c = 0; c < Cv; ++c) {
            const int st = c & 1;
            if (c + 1 < Cv) { load_stage(c + 1, st ^ 1); cp_commit(); cp_wait<1>(); }
            else            { cp_wait<0>(); }
            __syncthreads();

            const float* tbase = smem + st * 2 * TSZ;
            float* oc = ob + (size_t)c * HW;
#pragma unroll
            for (int k = 0; k < 2; ++k) {
                float s = 0.0f;
#pragma unroll
                for (int r = 0; r < Rv; ++r) {
                    const float* tb = tbase + r * TSZ + idesc[k][r];
                    s = fmaf(w4[k][r][0], tb[0],
                        fmaf(w4[k][r][1], tb[1],
                        fmaf(w4[k][r][2], tb[TCOLS],
                        fmaf(w4[k][r][3], tb[TCOLS + 1], s))));
                }
                oc[(size_t)(8 * k) * Wv] = s;
            }
            __syncthreads();
        }
    } else {
        for (int c = 0; c < Cv; ++c) {
            const int st = c & 1;
            if (c + 1 < Cv) { load_stage(c + 1, st ^ 1); cp_commit(); cp_wait<1>(); }
            else            { cp_wait<0>(); }
            __syncthreads();

            const float* tbase = smem + st * 2 * TSZ;
            float* oc = ob + (size_t)c * HW;
#pragma unroll
            for (int k = 0; k < 2; ++k) {
                float s = 0.0f;
#pragma unroll
                for (int r = 0; r < Rv; ++r) {
                    const int d = idesc[k][r];
                    float t0v, t1v, b0v, b1v;
                    if (d < 0x40000000) {
                        const float* tb = tbase + r * TSZ + d;
                        t0v = tb[0];      t1v = tb[1];
                        b0v = tb[TCOLS];  b1v = tb[TCOLS + 1];
                    } else {
                        const int gT = d & 0x1FFFF;
                        const int dv = (d >> 20) & 1;
                        const int gB = gT + ((d >> 21) & 1) * Wv;
                        const float* pc = (r ? pb1 : pb0) + (size_t)c * HW;
                        t0v = __ldg(pc + gT);  t1v = __ldg(pc + gT + dv);
                        b0v = __ldg(pc + gB);  b1v = __ldg(pc + gB + dv);
                    }
                    s = fmaf(w4[k][r][0], t0v,
                        fmaf(w4[k][r][1], t1v,
                        fmaf(w4[k][r][2], b0v,
                        fmaf(w4[k][r][3], b1v, s))));
                }
                oc[(size_t)(8 * k) * Wv] = s;
            }
            __syncthreads();
        }
    }
}

extern "C" void kernel_launch(void* const* d_in, const int* in_sizes, int n_in,
                              void* d_out, int out_size)
{
    const float* pred = (const float*)d_in[0];
    const float* mv   = (const float*)d_in[1];
    const float* wgt  = (const float*)d_in[2];
    float* out        = (float*)d_out;

    cudaFuncSetAttribute(mc_warp_kernel,
                         cudaFuncAttributeMaxDynamicSharedMemorySize, SMEM_BYTES);

    dim3 grid(Wv / 32, Hv / TILE_H, Bv);   // 16 x 16 x 4 = 1024 blocks
    mc_warp_kernel<<<grid, 256, SMEM_BYTES>>>(pred, mv, wgt, out);
}

// round 13
// speedup vs baseline: 1.4316x; 1.0055x over previous
#include <cuda_runtime.h>
#include <cstdint>

// MC_Module_Batch: bilinear backward warp + weight + sum over R.
// 2-stage cp.async pipeline, tight clamped tile window (48x31), 2 px/thread,
// 5 CTAs/SM. Escaping taps -> exact global fallback.
// pred [B,R,C,H,W], mv [B,R,2,H,W] (quarter-pel), weight [B,R,1,H,W] -> out [B,C,H,W]

#define Bv 4
#define Rv 2
#define Cv 19
#define Hv 256
#define Wv 512
#define HW (Hv * Wv)

#define TILE_H 16
#define PADY 7
#define PADX 8
#define TROWS (TILE_H + 2 * PADY + 1)  // 31
#define TCOLS 48
#define TC4   (TCOLS / 4)               // 12 float4 per row
#define TSZ   (TROWS * TCOLS)           // 1488 floats (5.8 KB)
#define TSZ4  (TSZ / 4)                 // 372 float4
#define SMEM_BYTES (2 * 2 * TSZ * 4)    // 23808 B

__device__ __forceinline__ void cp_async16(uint32_t smem, const void* g) {
    asm volatile("cp.async.cg.shared.global [%0], [%1], 16;" :: "r"(smem), "l"(g));
}
__device__ __forceinline__ void cp_commit() {
    asm volatile("cp.async.commit_group;");
}
template<int N> __device__ __forceinline__ void cp_wait() {
    asm volatile("cp.async.wait_group %0;" :: "n"(N));
}

__global__ __launch_bounds__(256, 5)
void mc_warp_kernel(const float* __restrict__ pred,
                    const float* __restrict__ mv,
                    const float* __restrict__ wgt,
                    float* __restrict__ out)
{
    extern __shared__ __align__(16) float smem[];   // [2 stages][2 r][TSZ]
    const uint32_t smem_u32 = (uint32_t)__cvta_generic_to_shared(smem);

    const int tid = threadIdx.x;
    const int tx  = tid & 31;
    const int ty  = tid >> 5;            // 0..7
    const int bx  = blockIdx.x, by = blockIdx.y, b = blockIdx.z;
    const int x0blk = bx * 32;
    const int y0blk = by * TILE_H;
    const int x = x0blk + tx;
    const int wbase = min(max(x0blk - PADX, 0), Wv - TCOLS);  // mult of 8 -> f4 aligned
    const int rowbase = y0blk - PADY;

    // ---- Precompute taps (2 px/thread, 2 r) ----
    // Fast: tile index of top-left tap (UNCLAMPED coords); taps at
    //   +0, +1, +TCOLS, +TCOLS+1. Row-clamped tile + exactly-zero weights on
    //   invalid taps keep this exact; window-escaping taps -> exact fallback.
    // Fallback (bit30): low17 = clamped global idx, bit20=dx, bit21=dy.
    float w4[2][2][4];
    int   idesc[2][2];
    int   fall = 0;
#pragma unroll
    for (int k = 0; k < 2; ++k) {
        const int y = y0blk + ty + 8 * k;
        const int pix = y * Wv + x;
#pragma unroll
        for (int r = 0; r < Rv; ++r) {
            const int nr = b * Rv + r;
            const float mvx = __ldg(mv + (size_t)(nr * 2) * HW + pix) * 0.25f;
            const float mvy = __ldg(mv + (size_t)(nr * 2 + 1) * HW + pix) * 0.25f;
            const float w   = __ldg(wgt + (size_t)nr * HW + pix);

            const float gx = (float)x + mvx;
            const float gy = (float)y + mvy;
            const float x0f = floorf(gx), y0f = floorf(gy);
            const float wx1 = gx - x0f, wx0 = 1.0f - wx1;
            const float wy1 = gy - y0f, wy0 = 1.0f - wy1;

            const int x0 = (int)x0f, y0 = (int)y0f;
            const int x1 = x0 + 1,   y1 = y0 + 1;

            const float vx0 = ((unsigned)x0 < (unsigned)Wv) ? 1.0f : 0.0f;
            const float vx1 = ((unsigned)x1 < (unsigned)Wv) ? 1.0f : 0.0f;
            const float vy0 = ((unsigned)y0 < (unsigned)Hv) ? 1.0f : 0.0f;
            const float vy1 = ((unsigned)y1 < (unsigned)Hv) ? 1.0f : 0.0f;

            w4[k][r][0] = wy0 * wx0 * vy0 * vx0 * w;
            w4[k][r][1] = wy0 * wx1 * vy0 * vx1 * w;
            w4[k][r][2] = wy1 * wx0 * vy1 * vx0 * w;
            w4[k][r][3] = wy1 * wx1 * vy1 * vx1 * w;

            const int tT = y0 - rowbase;   // UNCLAMPED
            const int tX = x0 - wbase;     // UNCLAMPED
            if ((unsigned)tT <= (TROWS - 2) && (unsigned)tX <= (TCOLS - 2)) {
                idesc[k][r] = tT * TCOLS + tX;
            } else {
                const int cx0 = min(max(x0, 0), Wv - 1);
                const int cx1 = min(max(x1, 0), Wv - 1);
                const int cy0 = min(max(y0, 0), Hv - 1);
                const int cy1 = min(max(y1, 0), Hv - 1);
                idesc[k][r] = 0x40000000 | ((cy1 - cy0) << 21)
                            | ((cx1 - cx0) << 20) | (cy0 * Wv + cx0);
                fall = 1;
            }
        }
    }
    const int anyfall = __syncthreads_or(fall);

    const float* pb0 = pred + (size_t)(b * Rv + 0) * Cv * HW;
    const float* pb1 = pred + (size_t)(b * Rv + 1) * Cv * HW;
    const int wb4 = wbase >> 2;

    float* ob = out + (size_t)b * Cv * HW + (size_t)(y0blk + ty) * Wv + x;

    auto load_stage = [&](int c, int st) {
        const float4* s0 = (const float4*)(pb0 + (size_t)c * HW);
        const float4* s1 = (const float4*)(pb1 + (size_t)c * HW);
        const uint32_t d0 = smem_u32 + (uint32_t)(st * 2 * TSZ) * 4u;
#pragma unroll
        for (int i = tid; i < TSZ4; i += 256) {
            const int row = i / TC4;
            const int c4  = i - row * TC4;
            const int gcy = min(max(rowbase + row, 0), Hv - 1);
            const int gi  = gcy * (Wv / 4) + wb4 + c4;
            cp_async16(d0 + (uint32_t)i * 16u, s0 + gi);
            cp_async16(d0 + (uint32_t)(TSZ * 4) + (uint32_t)i * 16u, s1 + gi);
        }
    };

    load_stage(0, 0);
    cp_commit();

    if (!anyfall) {
        for (int c = 0; c < Cv; ++c) {
            const int st = c & 1;
            if (c + 1 < Cv) { load_stage(c + 1, st ^ 1); cp_commit(); cp_wait<1>(); }
            else            { cp_wait<0>(); }
            __syncthreads();

            const float* tbase = smem + st * 2 * TSZ;
            float* oc = ob + (size_t)c * HW;
#pragma unroll
            for (int k = 0; k < 2; ++k) {
                float s = 0.0f;
#pragma unroll
                for (int r = 0; r < Rv; ++r) {
                    const float* tb = tbase + r * TSZ + idesc[k][r];
                    s = fmaf(w4[k][r][0], tb[0],
                        fmaf(w4[k][r][1], tb[1],
                        fmaf(w4[k][r][2], tb[TCOLS],
                        fmaf(w4[k][r][3], tb[TCOLS + 1], s))));
                }
                oc[(size_t)(8 * k) * Wv] = s;
            }
            __syncthreads();
        }
    } else {
        for (int c = 0; c < Cv; ++c) {
            const int st = c & 1;
            if (c + 1 < Cv) { load_stage(c + 1, st ^ 1); cp_commit(); cp_wait<1>(); }
            else            { cp_wait<0>(); }
            __syncthreads();

            const float* tbase = smem + st * 2 * TSZ;
            float* oc = ob + (size_t)c * HW;
#pragma unroll
            for (int k = 0; k < 2; ++k) {
                float s = 0.0f;
#pragma unroll
                for (int r = 0; r < Rv; ++r) {
                    const int d = idesc[k][r];
                    float t0v, t1v, b0v, b1v;
                    if (d < 0x40000000) {
                        const float* tb = tbase + r * TSZ + d;
                        t0v = tb[0];      t1v = tb[1];
                        b0v = tb[TCOLS];  b1v = tb[TCOLS + 1];
                    } else {
                        const int gT = d & 0x1FFFF;
                        const int dv = (d >> 20) & 1;
                        const int gB = gT + ((d >> 21) & 1) * Wv;
                        const float* pc = (r ? pb1 : pb0) + (size_t)c * HW;
                        t0v = __ldg(pc + gT);  t1v = __ldg(pc + gT + dv);
                        b0v = __ldg(pc + gB);  b1v = __ldg(pc + gB + dv);
                    }
                    s = fmaf(w4[k][r][0], t0v,
                        fmaf(w4[k][r][1], t1v,
                        fmaf(w4[k][r][2], b0v,
                        fmaf(w4[k][r][3], b1v, s))));
                }
                oc[(size_t)(8 * k) * Wv] = s;
            }
            __syncthreads();
        }
    }
}

extern "C" void kernel_launch(void* const* d_in, const int* in_sizes, int n_in,
                              void* d_out, int out_size)
{
    const float* pred = (const float*)d_in[0];
    const float* mv   = (const float*)d_in[1];
    const float* wgt  = (const float*)d_in[2];
    float* out        = (float*)d_out;

    cudaFuncSetAttribute(mc_warp_kernel,
                         cudaFuncAttributeMaxDynamicSharedMemorySize, SMEM_BYTES);

    dim3 grid(Wv / 32, Hv / TILE_H, Bv);   // 16 x 16 x 4 = 1024 blocks
    mc_warp_kernel<<<grid, 256, SMEM_BYTES>>>(pred, mv, wgt, out);
}